// round 15
// baseline (speedup 1.0000x reference)
#include <cuda_runtime.h>
#include <cuda_bf16.h>
#include <mma.h>
#include <math.h>
using namespace nvcuda;

#define NCB   10
#define KCB   2048
#define DD    256
#define SEMD  256
#define W2VD  1024
#define BT    16384
#define ZQ_ELEMS (BT*DD)
#define CODES_OFF ZQ_ELEMS
#define VQ_OFF   (CODES_OFF + BT*NCB)
#define SEM_OFF  (VQ_OFF + 1)
#define APAD  68
#define CMAR  0.04f              // screening margin coeff (2.5x rigorous bound)
#define CAP   16

// scr tiling: 136 CTAs x 112 tokens + 12 CTAs x 96 = 16384, grid 148 (1 CTA/SM)
#define N112  136
#define OFF96 (N112*112)         // 15232

// smem layout (float indices) for k_scr
#define SA_ABF  0                // bf16 [112][272]          = 15232 floats
#define SA_BST  15232            // bf16 [3][128][16]        =  3072 floats
#define SA_DSC  18304            // f32  [8 warps][320]      =  2560 floats
#define SA_ENS  20864            // [2048]
#define SA_PMS  22912            // [2048] CMAR*||e||
#define SA_XXS  24960            // [112]
#define SA_WIN  25072            // [112] int
#define SA_TOT  25184            // 100,736 B

// -------- device scratch --------
__device__ float g_res[ZQ_ELEMS];             // fp32 residual
__device__ float g_zq1[ZQ_ELEMS];             // z_q of cb0 for semantic head
__device__ __nv_bfloat16 g_Ebf[NCB*KCB*DD];   // bf16 E, plain row-major (10.5 MB)
__device__ float g_en[NCB*KCB];
__device__ float g_me[NCB*KCB];
__device__ float g_vqp[NCB];
__device__ float g_semsum;

// ---- fp32x2 helpers (k_sem) ----
__device__ __forceinline__ void fma2(unsigned long long& d,
                                     unsigned long long a, unsigned long long b) {
    asm("fma.rn.f32x2 %0, %1, %2, %0;" : "+l"(d) : "l"(a), "l"(b));
}
__device__ __forceinline__ unsigned long long dup2(float a) {
    unsigned long long r;
    asm("mov.b64 %0, {%1, %1};" : "=l"(r) : "f"(a));
    return r;
}
__device__ __forceinline__ void unpk(float& lo, float& hi, unsigned long long v) {
    asm("mov.b64 {%0, %1}, %2;" : "=f"(lo), "=f"(hi) : "l"(v));
}
__device__ __forceinline__ void cp16(void* smem_dst, const void* gsrc) {
    unsigned s = (unsigned)__cvta_generic_to_shared(smem_dst);
    asm volatile("cp.async.cg.shared.global [%0], [%1], 16;" :: "r"(s), "l"(gsrc));
}

// ---------------- prep: bf16 copy of E ----------------
__global__ void k_bfe(const float* __restrict__ E) {
    int i = blockIdx.x * blockDim.x + threadIdx.x;
    g_Ebf[i] = __float2bfloat16(E[i]);
}

// ---------------- codeword norms (legacy order) + ||e|| ----------------
__global__ void k_enorm(const float* __restrict__ E) {
    int w = (blockIdx.x * blockDim.x + threadIdx.x) >> 5;
    int lane = threadIdx.x & 31;
    if (w >= NCB * KCB) return;
    const float* e = E + (size_t)w * DD;
    float s = 0.f;
    #pragma unroll
    for (int k = 0; k < 8; k++) { float v = e[lane + 32 * k]; s += v * v; }
    #pragma unroll
    for (int off = 16; off; off >>= 1) s += __shfl_down_sync(0xffffffffu, s, off);
    if (!lane) { g_en[w] = s; g_me[w] = sqrtf(s); }
}

__global__ void k_init() {
    int i = threadIdx.x;
    if (i < NCB) g_vqp[i] = 0.f;
    if (i == NCB) g_semsum = 0.f;
}

// exact fp32 distance: bitwise-identical to legacy per-(token,cw) chain
__device__ __forceinline__ float exact_dist(const float* rrow, const float* erow,
                                            float xx, float en) {
    float dot = 0.f;
    #pragma unroll 8
    for (int d = 0; d < DD; d++) dot = fmaf(rrow[d], __ldg(&erow[d]), dot);
    return (xx - 2.0f * dot) + en;
}

// ---------------- RVQ via wmma-bf16 screening + exact rescore ----------------
template<int NM>   // live 16-token m-tiles per CTA (7 or 6)
__device__ __forceinline__ void scr_body(
    int m0, const float* __restrict__ z, const float* __restrict__ E,
    float* __restrict__ out, float* sm, int tid, int lane, int wy)
{
    __nv_bfloat16* Abf = (__nv_bfloat16*)(sm + SA_ABF);   // [112][272]
    __nv_bfloat16* Bst = (__nv_bfloat16*)(sm + SA_BST);   // [3][128][16]
    float* Dsc = sm + SA_DSC;                             // [8][320]
    float* ens = sm + SA_ENS;
    float* pms = sm + SA_PMS;
    float* xxs = sm + SA_XXS;
    int*   win = (int*)(sm + SA_WIN);
    const int MT = NM * 16;

    // residual <- z; initial ||x||^2 (legacy chain)
    {
        const float4* Z4 = reinterpret_cast<const float4*>(z + (size_t)m0 * DD);
        float4* R4 = reinterpret_cast<float4*>(g_res + (size_t)m0 * DD);
        for (int i = tid; i < MT * 64; i += 256) R4[i] = Z4[i];
    }
    if (wy < NM) {
        for (int r = 0; r < 16; r++) {
            int t = wy * 16 + r;
            const float* row = z + (size_t)(m0 + t) * DD;
            float s = 0.f;
            #pragma unroll
            for (int k = 0; k < 8; k++) { float v = row[lane + 32 * k]; s += v * v; }
            #pragma unroll
            for (int off = 16; off; off >>= 1) s += __shfl_down_sync(0xffffffffu, s, off);
            if (!lane) xxs[t] = s;
        }
    }
    __syncthreads();

    for (int cb = 0; cb < NCB; cb++) {
        // stage en / margin tables
        {
            const float4* e4 = reinterpret_cast<const float4*>(g_en + cb * KCB);
            const float4* m4 = reinterpret_cast<const float4*>(g_me + cb * KCB);
            for (int i = tid; i < 512; i += 256) {
                *reinterpret_cast<float4*>(&ens[i * 4]) = e4[i];
                float4 mv = m4[i];
                mv.x *= CMAR; mv.y *= CMAR; mv.z *= CMAR; mv.w *= CMAR;
                *reinterpret_cast<float4*>(&pms[i * 4]) = mv;
            }
        }
        // residual -> bf16 Abf
        for (int i = tid; i < MT * 128; i += 256) {
            int r = i >> 7, dp = i & 127;
            float2 p = *reinterpret_cast<const float2*>(g_res + (size_t)(m0 + r) * DD + dp * 2);
            unsigned u;
            asm("cvt.rn.bf16x2.f32 %0, %1, %2;" : "=r"(u) : "f"(p.y), "f"(p.x));
            *reinterpret_cast<unsigned*>(&Abf[r * 272 + dp * 2]) = u;
        }
        __syncthreads();

        float xx = 0.f, xn = 0.f, A = INFINITY;
        int cnt = 0, ovf = 0;
        int ck[CAP]; float clo[CAP];
        if (wy < NM) { xx = xxs[wy * 16 + (lane & 15)]; xn = sqrtf(xx); }

        // B chunk stager: chunk q = (nc, kc) -> [128 cw][16 d] bf16 (4 KB)
        auto issue = [&](int q) {
            int nc = q >> 4, kc = q & 15;
            int cw = tid >> 1, hf = tid & 1;
            const __nv_bfloat16* src = g_Ebf
                + ((size_t)(cb * KCB + nc * 128 + cw)) * DD + kc * 16 + hf * 8;
            cp16(&Bst[(q % 3) * 2048 + cw * 16 + hf * 8], src);
            asm volatile("cp.async.commit_group;");
        };
        issue(0); issue(1);

        wmma::fragment<wmma::accumulator, 16, 16, 16, float> acc[8];

        for (int q = 0; q < 256; q++) {
            int nc = q >> 4, kc = q & 15;
            if (kc == 0 && wy < NM)
                #pragma unroll
                for (int nf = 0; nf < 8; nf++) wmma::fill_fragment(acc[nf], 0.0f);

            if (q < 255) asm volatile("cp.async.wait_group 1;");
            else         asm volatile("cp.async.wait_group 0;");
            __syncthreads();
            if (q + 2 < 256) issue(q + 2);

            if (wy < NM) {
                wmma::fragment<wmma::matrix_a, 16, 16, 16, __nv_bfloat16, wmma::row_major> af;
                wmma::load_matrix_sync(af, Abf + wy * 16 * 272 + kc * 16, 272);
                const __nv_bfloat16* bp = Bst + (q % 3) * 2048;
                #pragma unroll
                for (int nf = 0; nf < 8; nf++) {
                    wmma::fragment<wmma::matrix_b, 16, 16, 16, __nv_bfloat16, wmma::col_major> bf;
                    wmma::load_matrix_sync(bf, bp + nf * 16 * 16, 16);
                    wmma::mma_sync(acc[nf], af, bf, acc[nf]);
                }
            }

            if (kc == 15 && wy < NM) {          // screen this 128-cw chunk
                float* dw = Dsc + wy * 320;
                int tt = lane & 15, h = lane >> 4;
                #pragma unroll 1
                for (int nf = 0; nf < 8; nf++) {
                    wmma::store_matrix_sync(dw, acc[nf], 20, wmma::mem_col_major);
                    __syncwarp();
                    #pragma unroll
                    for (int c = 0; c < 8; c++) {
                        int n = h * 8 + c;
                        int k = nc * 128 + nf * 16 + n;
                        float dot = dw[n * 20 + tt];
                        float s = (xx - 2.0f * dot) + ens[k];
                        float mg = xn * pms[k];
                        float lo = s - mg;
                        if (lo <= A) {
                            if (cnt == CAP) {
                                int nn = 0;
                                for (int i2 = 0; i2 < CAP; i2++)
                                    if (clo[i2] <= A) { ck[nn] = ck[i2]; clo[nn] = clo[i2]; nn++; }
                                cnt = nn;
                            }
                            if (cnt < CAP) { ck[cnt] = k; clo[cnt] = lo; cnt++; }
                            else ovf = 1;
                        }
                        A = fminf(A, s + mg);
                    }
                    __syncwarp();
                }
            }
        }

        // winner resolution: lanes (tt, tt+16) of warp wy share token wy*16+tt
        if (wy < NM) {
            int tt = lane & 15, h = lane >> 4;
            int t = wy * 16 + tt;
            int gt = m0 + t;
            const float* rrow = g_res + (size_t)gt * DD;
            float Af = fminf(A, __shfl_xor_sync(0xffffffffu, A, 16));
            int o2 = ovf | __shfl_xor_sync(0xffffffffu, ovf, 16);

            float bv = INFINITY; int bi = 0x7fffffff;
            if (o2) {
                if (h == 0) {                           // exact full scan (rare)
                    for (int k = 0; k < KCB; k++) {
                        float s = exact_dist(rrow, E + ((size_t)cb * KCB + k) * DD, xx, ens[k]);
                        if (s < bv) { bv = s; bi = k; }
                    }
                }
            } else {
                int ns = 0, sk[CAP];
                for (int i = 0; i < cnt; i++)
                    if (clo[i] <= Af) sk[ns++] = ck[i];
                for (int i = 0; i < ns; i++) {          // ascending k
                    int k = sk[i];
                    float s = exact_dist(rrow, E + ((size_t)cb * KCB + k) * DD, xx, ens[k]);
                    if (s < bv || (s == bv && k < bi)) { bv = s; bi = k; }
                }
            }
            float ov = __shfl_xor_sync(0xffffffffu, bv, 16);
            int   oi = __shfl_xor_sync(0xffffffffu, bi, 16);
            if (ov < bv || (ov == bv && oi < bi)) { bv = ov; bi = oi; }
            if (h == 0) win[t] = bi;
        }
        __syncthreads();

        // straight-through update (legacy fp order); warp wy tokens wy*16..+15
        if (wy < NM) {
            float sl = 0.f;
            for (int r = 0; r < 16; r++) {
                int t = wy * 16 + r;
                int tok = m0 + t;
                int idx = win[t];
                const float* qrow = E + ((size_t)cb * KCB + idx) * DD;
                float* rrow = g_res + (size_t)tok * DD;
                float* orow = out + (size_t)tok * DD;
                float sx = 0.f;
                #pragma unroll
                for (int j = 0; j < 8; j++) {
                    int d = lane + 32 * j;
                    float rr = rrow[d];
                    float q  = __ldg(&qrow[d]);
                    float df = q - rr;                 // fl(q - r)
                    float zq = rr + df;                // straight-through, jax order
                    float nr = rr - zq;                // new residual
                    if (cb == 0) { orow[d] = zq; g_zq1[(size_t)tok * DD + d] = zq; }
                    else orow[d] += zq;
                    rrow[d] = nr;
                    sl += df * df;
                    sx += nr * nr;
                }
                #pragma unroll
                for (int off = 16; off; off >>= 1) sx += __shfl_down_sync(0xffffffffu, sx, off);
                if (!lane) {
                    xxs[t] = sx;
                    out[CODES_OFF + tok * NCB + cb] = (float)idx;
                }
            }
            #pragma unroll
            for (int off = 16; off; off >>= 1) sl += __shfl_xor_sync(0xffffffffu, sl, off);
            if (!lane) atomicAdd(&g_vqp[cb], sl);
        }
        __syncthreads();   // updates visible before next cb's convert/screen
    }
}

__global__ void __launch_bounds__(256, 1)
k_scr(const float* __restrict__ z, const float* __restrict__ E, float* __restrict__ out) {
    extern __shared__ float sm[];
    int tid = threadIdx.x;
    int lane = tid & 31, wy = tid >> 5;
    int b = blockIdx.x;
    if (b < N112) scr_body<7>(b * 112, z, E, out, sm, tid, lane, wy);
    else          scr_body<6>(OFF96 + (b - N112) * 96, z, E, out, sm, tid, lane, wy);
}

// ---------------- fused semantic head (verbatim from R12, passing) ----------------
__global__ void __launch_bounds__(256, 2)
k_sem(const float* __restrict__ W1, const float* __restrict__ b1,
      const float* __restrict__ W2, const float* __restrict__ b2,
      const float* __restrict__ tgt) {
    extern __shared__ float sm[];
    float* Asm = sm;
    float* Bs  = sm + 256 * APAD;
    int tid = threadIdx.x, tx = tid & 15, ty = tid >> 4;
    int m0 = blockIdx.x * 64;

    const float4* Ag = reinterpret_cast<const float4*>(g_zq1 + (size_t)m0 * DD);
    #pragma unroll
    for (int i = 0; i < 16; i++) {
        int f = tid + 256 * i;
        int tok = f >> 6, seg = f & 63;
        float4 v = Ag[f];
        int db = seg * 4;
        Asm[(db + 0) * APAD + tok] = v.x;
        Asm[(db + 1) * APAD + tok] = v.y;
        Asm[(db + 2) * APAD + tok] = v.z;
        Asm[(db + 3) * APAD + tok] = v.w;
    }
    __syncthreads();

    unsigned long long hacc[4][8];
    #pragma unroll
    for (int r = 0; r < 4; r++)
        #pragma unroll
        for (int u = 0; u < 8; u++) hacc[r][u] = 0ull;

    for (int nb = 0; nb < 4; nb++) {
        int n0 = nb * 64;
        for (int dc = 0; dc < 16; dc++) {
            int dk = tid >> 4, nseg = tid & 15;
            float4 v = *reinterpret_cast<const float4*>(&W1[(size_t)(dc * 16 + dk) * SEMD + n0 + nseg * 4]);
            *reinterpret_cast<float4*>(&Bs[dk * APAD + nseg * 4]) = v;
            __syncthreads();
            #pragma unroll
            for (int kk = 0; kk < 16; kk++) {
                float4 av = *reinterpret_cast<const float4*>(&Asm[(dc * 16 + kk) * APAD + ty * 4]);
                ulonglong2 bb = *reinterpret_cast<const ulonglong2*>(&Bs[kk * APAD + tx * 4]);
                float a[4] = {av.x, av.y, av.z, av.w};
                #pragma unroll
                for (int r = 0; r < 4; r++) {
                    unsigned long long a2 = dup2(a[r]);
                    fma2(hacc[r][nb * 2 + 0], a2, bb.x);
                    fma2(hacc[r][nb * 2 + 1], a2, bb.y);
                }
            }
            __syncthreads();
        }
    }

    #pragma unroll
    for (int r = 0; r < 4; r++)
        #pragma unroll
        for (int u = 0; u < 8; u++) {
            int m = ty * 4 + r;
            int n = (u >> 1) * 64 + tx * 4 + (u & 1) * 2;
            float lo, hi;
            unpk(lo, hi, hacc[r][u]);
            float x0 = lo + __ldg(&b1[n]);
            float x1 = hi + __ldg(&b1[n + 1]);
            Asm[n * APAD + m]       = 0.5f * x0 * (1.0f + erff(x0 * 0.70710678118654752f));
            Asm[(n + 1) * APAD + m] = 0.5f * x1 * (1.0f + erff(x1 * 0.70710678118654752f));
        }
    __syncthreads();

    float ls = 0.f;
    for (int n0b = 0; n0b < 16; n0b++) {
        int n0 = n0b * 64;
        unsigned long long acc[4][2];
        #pragma unroll
        for (int r = 0; r < 4; r++) { acc[r][0] = 0ull; acc[r][1] = 0ull; }

        for (int dc = 0; dc < 16; dc++) {
            int dk = tid >> 4, nseg = tid & 15;
            float4 v = *reinterpret_cast<const float4*>(&W2[(size_t)(dc * 16 + dk) * W2VD + n0 + nseg * 4]);
            *reinterpret_cast<float4*>(&Bs[dk * APAD + nseg * 4]) = v;
            __syncthreads();
            #pragma unroll
            for (int kk = 0; kk < 16; kk++) {
                float4 av = *reinterpret_cast<const float4*>(&Asm[(dc * 16 + kk) * APAD + ty * 4]);
                ulonglong2 bb = *reinterpret_cast<const ulonglong2*>(&Bs[kk * APAD + tx * 4]);
                float a[4] = {av.x, av.y, av.z, av.w};
                #pragma unroll
                for (int r = 0; r < 4; r++) {
                    unsigned long long a2 = dup2(a[r]);
                    fma2(acc[r][0], a2, bb.x);
                    fma2(acc[r][1], a2, bb.y);
                }
            }
            __syncthreads();
        }

        #pragma unroll
        for (int r = 0; r < 4; r++)
            #pragma unroll
            for (int q = 0; q < 2; q++) {
                int m = m0 + ty * 4 + r, n = n0 + tx * 4 + q * 2;
                float lo, hi;
                unpk(lo, hi, acc[r][q]);
                float p0 = lo + __ldg(&b2[n]);
                float p1 = hi + __ldg(&b2[n + 1]);
                float d0 = p0 - __ldg(&tgt[(size_t)m * W2VD + n]);
                float d1 = p1 - __ldg(&tgt[(size_t)m * W2VD + n + 1]);
                ls += d0 * d0;
                ls += d1 * d1;
            }
    }

    __shared__ float red[8];
    int lane = tid & 31, w = tid >> 5;
    #pragma unroll
    for (int off = 16; off; off >>= 1) ls += __shfl_xor_sync(0xffffffffu, ls, off);
    if (!lane) red[w] = ls;
    __syncthreads();
    if (tid < 8) {
        float t = red[tid];
        #pragma unroll
        for (int off = 4; off; off >>= 1) t += __shfl_xor_sync(0xffu, t, off);
        if (tid == 0) atomicAdd(&g_semsum, t);
    }
}

// ---------------- finalize scalars ----------------
__global__ void k_fin(float* __restrict__ out) {
    if (threadIdx.x == 0) {
        float vq = 0.f;
        #pragma unroll
        for (int i = 0; i < NCB; i++) {
            float m = g_vqp[i] * (1.0f / 4194304.0f);
            vq += m + 0.25f * m;
        }
        out[VQ_OFF] = vq;
        out[SEM_OFF] = g_semsum * (1.0f / 16777216.0f);
    }
}

// ---------------- launch ----------------
extern "C" void kernel_launch(void* const* d_in, const int* in_sizes, int n_in,
                              void* d_out, int out_size) {
    const float* z   = (const float*)d_in[0];
    const float* w2v = (const float*)d_in[1];
    const float* E   = (const float*)d_in[2];
    const float* W1  = (const float*)d_in[3];
    const float* b1  = (const float*)d_in[4];
    const float* W2  = (const float*)d_in[5];
    const float* b2  = (const float*)d_in[6];
    float* out = (float*)d_out;

    const int SCR_SMEM = SA_TOT * 4;                     // 100,736 B
    const int SEM_SMEM = (256 * APAD + 16 * APAD) * 4;   // 73,984 B
    cudaFuncSetAttribute(k_scr, cudaFuncAttributeMaxDynamicSharedMemorySize, SCR_SMEM);
    cudaFuncSetAttribute(k_sem, cudaFuncAttributeMaxDynamicSharedMemorySize, SEM_SMEM);

    k_bfe<<<(NCB * KCB * DD) / 256, 256>>>(E);
    k_enorm<<<(NCB * KCB * 32 + 255) / 256, 256>>>(E);
    k_init<<<1, 32>>>();

    k_scr<<<148, 256, SCR_SMEM>>>(z, E, out);

    k_sem<<<BT / 64, 256, SEM_SMEM>>>(W1, b1, W2, b2, w2v);
    k_fin<<<1, 32>>>(out);
}

// round 17
// speedup vs baseline: 5.2547x; 5.2547x over previous
#include <cuda_runtime.h>
#include <cuda_bf16.h>
#include <mma.h>
#include <math.h>
using namespace nvcuda;

#define NCB   10
#define KCB   2048
#define DD    256
#define SEMD  256
#define W2VD  1024
#define BT    16384
#define ZQ_ELEMS (BT*DD)
#define CODES_OFF ZQ_ELEMS
#define VQ_OFF   (CODES_OFF + BT*NCB)
#define SEM_OFF  (VQ_OFF + 1)
#define APAD  68
#define CMAR  0.04f              // screening margin coeff (validated in R15)

// scr tiling: 136 CTAs x 112 tokens + 12 CTAs x 96 = 16384, grid 148 (1 CTA/SM)
#define N112  136
#define OFF96 (N112*112)         // 15232

// smem layout (float indices) for k_scr
#define SB_B    0                // bf16 [2][64 cw][256 d]  = 16384 floats (64 KB)
#define SB_ABF  16384            // bf16 [112][272]         = 15232 floats
#define SB_DSC  31616            // f32  [8 warps][320]
#define SB_ENS  34176            // [2048]
#define SB_PMS  36224            // [2048] CMAR*||e||
#define SB_XXS  38272            // [112]
#define SB_WIN  38400            // [112] int
#define SB_TOT  38528            // 154,112 B

// -------- device scratch --------
__device__ float g_res[ZQ_ELEMS];             // fp32 residual
__device__ float g_zq1[ZQ_ELEMS];             // z_q of cb0 for semantic head
__device__ __nv_bfloat16 g_Ebf[NCB*KCB*DD];   // bf16 E, row-major (10.5 MB)
__device__ float g_en[NCB*KCB];
__device__ float g_me[NCB*KCB];
__device__ float g_vqp[NCB];
__device__ float g_semsum;

// ---- fp32x2 helpers (k_sem) ----
__device__ __forceinline__ void fma2(unsigned long long& d,
                                     unsigned long long a, unsigned long long b) {
    asm("fma.rn.f32x2 %0, %1, %2, %0;" : "+l"(d) : "l"(a), "l"(b));
}
__device__ __forceinline__ unsigned long long dup2(float a) {
    unsigned long long r;
    asm("mov.b64 %0, {%1, %1};" : "=l"(r) : "f"(a));
    return r;
}
__device__ __forceinline__ void unpk(float& lo, float& hi, unsigned long long v) {
    asm("mov.b64 {%0, %1}, %2;" : "=f"(lo), "=f"(hi) : "l"(v));
}
__device__ __forceinline__ void cp16(void* smem_dst, const void* gsrc) {
    unsigned s = (unsigned)__cvta_generic_to_shared(smem_dst);
    asm volatile("cp.async.cg.shared.global [%0], [%1], 16;" :: "r"(s), "l"(gsrc));
}

// ---------------- prep: bf16 copy of E ----------------
__global__ void k_bfe(const float* __restrict__ E) {
    int i = blockIdx.x * blockDim.x + threadIdx.x;
    g_Ebf[i] = __float2bfloat16(E[i]);
}

// ---------------- codeword norms (legacy order) + ||e|| ----------------
__global__ void k_enorm(const float* __restrict__ E) {
    int w = (blockIdx.x * blockDim.x + threadIdx.x) >> 5;
    int lane = threadIdx.x & 31;
    if (w >= NCB * KCB) return;
    const float* e = E + (size_t)w * DD;
    float s = 0.f;
    #pragma unroll
    for (int k = 0; k < 8; k++) { float v = e[lane + 32 * k]; s += v * v; }
    #pragma unroll
    for (int off = 16; off; off >>= 1) s += __shfl_down_sync(0xffffffffu, s, off);
    if (!lane) { g_en[w] = s; g_me[w] = sqrtf(s); }
}

__global__ void k_init() {
    int i = threadIdx.x;
    if (i < NCB) g_vqp[i] = 0.f;
    if (i == NCB) g_semsum = 0.f;
}

// exact fp32 distance: bitwise-identical to legacy per-(token,cw) chain
__device__ __forceinline__ float exact_dist(const float* rrow, const float* erow,
                                            float xx, float en) {
    float dot = 0.f;
    #pragma unroll 8
    for (int d = 0; d < DD; d++) dot = fmaf(rrow[d], __ldg(&erow[d]), dot);
    return (xx - 2.0f * dot) + en;
}

// ---------------- RVQ via wmma-bf16 screening + immediate exact rescore ----------------
template<int NM>   // live 16-token m-tiles per CTA (7 or 6)
__device__ __forceinline__ void scr_body(
    int m0, const float* __restrict__ z, const float* __restrict__ E,
    float* __restrict__ out, float* sm, int tid, int lane, int wy)
{
    __nv_bfloat16* Bst = (__nv_bfloat16*)(sm + SB_B);     // [2][64][256]
    __nv_bfloat16* Abf = (__nv_bfloat16*)(sm + SB_ABF);   // [112][272]
    float* Dsc = sm + SB_DSC;
    float* ens = sm + SB_ENS;
    float* pms = sm + SB_PMS;
    float* xxs = sm + SB_XXS;
    int*   win = (int*)(sm + SB_WIN);
    const int MT = NM * 16;

    // residual <- z; initial ||x||^2 (legacy chain)
    {
        const float4* Z4 = reinterpret_cast<const float4*>(z + (size_t)m0 * DD);
        float4* R4 = reinterpret_cast<float4*>(g_res + (size_t)m0 * DD);
        for (int i = tid; i < MT * 64; i += 256) R4[i] = Z4[i];
    }
    if (wy < NM) {
        for (int r = 0; r < 16; r++) {
            int t = wy * 16 + r;
            const float* row = z + (size_t)(m0 + t) * DD;
            float s = 0.f;
            #pragma unroll
            for (int k = 0; k < 8; k++) { float v = row[lane + 32 * k]; s += v * v; }
            #pragma unroll
            for (int off = 16; off; off >>= 1) s += __shfl_down_sync(0xffffffffu, s, off);
            if (!lane) xxs[t] = s;
        }
    }
    __syncthreads();

    for (int cb = 0; cb < NCB; cb++) {
        // stage en / margin tables
        {
            const float4* e4 = reinterpret_cast<const float4*>(g_en + cb * KCB);
            const float4* m4 = reinterpret_cast<const float4*>(g_me + cb * KCB);
            for (int i = tid; i < 512; i += 256) {
                *reinterpret_cast<float4*>(&ens[i * 4]) = e4[i];
                float4 mv = m4[i];
                mv.x *= CMAR; mv.y *= CMAR; mv.z *= CMAR; mv.w *= CMAR;
                *reinterpret_cast<float4*>(&pms[i * 4]) = mv;
            }
        }
        // residual -> bf16 Abf
        for (int i = tid; i < MT * 128; i += 256) {
            int r = i >> 7, dp = i & 127;
            float2 p = *reinterpret_cast<const float2*>(g_res + (size_t)(m0 + r) * DD + dp * 2);
            unsigned u;
            asm("cvt.rn.bf16x2.f32 %0, %1, %2;" : "=r"(u) : "f"(p.y), "f"(p.x));
            *reinterpret_cast<unsigned*>(&Abf[r * 272 + dp * 2]) = u;
        }

        // B chunk stager: chunk q = 64 contiguous codewords x 256 d (32 KB contiguous)
        auto issue = [&](int q) {
            const char* src = (const char*)(g_Ebf + ((size_t)(cb * KCB + q * 64)) * DD);
            char* dst = (char*)Bst + (q & 1) * 32768;
            #pragma unroll
            for (int i = 0; i < 8; i++)
                cp16(dst + (tid + 256 * i) * 16, src + (tid + 256 * i) * 16);
            asm volatile("cp.async.commit_group;");
        };
        issue(0); issue(1);

        int tt = lane & 15, h = lane >> 4;
        float xx = 0.f, xn = 0.f;
        const float* rrow = g_res + (size_t)(m0 + wy * 16 + tt) * DD;
        if (wy < NM) { xx = xxs[wy * 16 + tt]; xn = sqrtf(xx); }
        float A = INFINITY, bv = INFINITY;
        int bi = 0x7fffffff;

        for (int q = 0; q < 32; q++) {
            if (q < 31) asm volatile("cp.async.wait_group 1;");
            else        asm volatile("cp.async.wait_group 0;");
            __syncthreads();

            if (wy < NM) {
                const __nv_bfloat16* Bp = Bst + (q & 1) * 16384;
                wmma::fragment<wmma::accumulator, 16, 16, 16, float> acc[4];
                #pragma unroll
                for (int nf = 0; nf < 4; nf++) wmma::fill_fragment(acc[nf], 0.0f);
                #pragma unroll 1
                for (int kc = 0; kc < 16; kc++) {
                    wmma::fragment<wmma::matrix_a, 16, 16, 16, __nv_bfloat16, wmma::row_major> af;
                    wmma::load_matrix_sync(af, Abf + (wy * 16) * 272 + kc * 16, 272);
                    #pragma unroll
                    for (int nf = 0; nf < 4; nf++) {
                        wmma::fragment<wmma::matrix_b, 16, 16, 16, __nv_bfloat16, wmma::col_major> bf;
                        wmma::load_matrix_sync(bf, Bp + (nf * 16) * 256 + kc * 16, 256);
                        wmma::mma_sync(acc[nf], af, bf, acc[nf]);
                    }
                }
                // screen + immediate exact rescore (no candidate arrays)
                float* dw = Dsc + wy * 320;
                #pragma unroll 1
                for (int nf = 0; nf < 4; nf++) {
                    wmma::store_matrix_sync(dw, acc[nf], 20, wmma::mem_col_major);
                    __syncwarp();
                    #pragma unroll
                    for (int c = 0; c < 8; c++) {
                        int n = h * 8 + c;
                        int k = q * 64 + nf * 16 + n;
                        float dot = dw[n * 20 + tt];
                        float s = (xx - 2.0f * dot) + ens[k];
                        float mg = xn * pms[k];
                        if (s - mg <= A) {
                            float se = exact_dist(rrow, E + ((size_t)cb * KCB + k) * DD,
                                                  xx, ens[k]);
                            if (se < bv || (se == bv && k < bi)) { bv = se; bi = k; }
                        }
                        A = fminf(A, s + mg);
                    }
                    __syncwarp();
                }
            }
            __syncthreads();              // compute done before buf (q&1) is re-issued
            if (q + 2 < 32) issue(q + 2);
        }

        // merge the two half-lanes sharing each token (lex (value,index) min)
        if (wy < NM) {
            float ov = __shfl_xor_sync(0xffffffffu, bv, 16);
            int   oi = __shfl_xor_sync(0xffffffffu, bi, 16);
            if (ov < bv || (ov == bv && oi < bi)) { bv = ov; bi = oi; }
            if (h == 0) win[wy * 16 + tt] = bi;
        }
        __syncthreads();

        // straight-through update (legacy fp order); warp wy tokens wy*16..+15
        if (wy < NM) {
            float sl = 0.f;
            for (int r = 0; r < 16; r++) {
                int t = wy * 16 + r;
                int tok = m0 + t;
                int idx = win[t];
                const float* qrow = E + ((size_t)cb * KCB + idx) * DD;
                float* rr2 = g_res + (size_t)tok * DD;
                float* orow = out + (size_t)tok * DD;
                float sx = 0.f;
                #pragma unroll
                for (int j = 0; j < 8; j++) {
                    int d = lane + 32 * j;
                    float rr = rr2[d];
                    float qv = __ldg(&qrow[d]);
                    float df = qv - rr;                // fl(q - r)
                    float zq = rr + df;                // straight-through, jax order
                    float nr = rr - zq;                // new residual
                    if (cb == 0) { orow[d] = zq; g_zq1[(size_t)tok * DD + d] = zq; }
                    else orow[d] += zq;
                    rr2[d] = nr;
                    sl += df * df;
                    sx += nr * nr;
                }
                #pragma unroll
                for (int off = 16; off; off >>= 1) sx += __shfl_down_sync(0xffffffffu, sx, off);
                if (!lane) {
                    xxs[t] = sx;
                    out[CODES_OFF + tok * NCB + cb] = (float)idx;
                }
            }
            #pragma unroll
            for (int off = 16; off; off >>= 1) sl += __shfl_xor_sync(0xffffffffu, sl, off);
            if (!lane) atomicAdd(&g_vqp[cb], sl);
        }
        __syncthreads();   // updates visible before next cb's convert/screen
    }
}

__global__ void __launch_bounds__(256, 1)
k_scr(const float* __restrict__ z, const float* __restrict__ E, float* __restrict__ out) {
    extern __shared__ float sm[];
    int tid = threadIdx.x;
    int lane = tid & 31, wy = tid >> 5;
    int b = blockIdx.x;
    if (b < N112) scr_body<7>(b * 112, z, E, out, sm, tid, lane, wy);
    else          scr_body<6>(OFF96 + (b - N112) * 96, z, E, out, sm, tid, lane, wy);
}

// ---------------- fused semantic head (verbatim, passing) ----------------
__global__ void __launch_bounds__(256, 2)
k_sem(const float* __restrict__ W1, const float* __restrict__ b1,
      const float* __restrict__ W2, const float* __restrict__ b2,
      const float* __restrict__ tgt) {
    extern __shared__ float sm[];
    float* Asm = sm;
    float* Bs  = sm + 256 * APAD;
    int tid = threadIdx.x, tx = tid & 15, ty = tid >> 4;
    int m0 = blockIdx.x * 64;

    const float4* Ag = reinterpret_cast<const float4*>(g_zq1 + (size_t)m0 * DD);
    #pragma unroll
    for (int i = 0; i < 16; i++) {
        int f = tid + 256 * i;
        int tok = f >> 6, seg = f & 63;
        float4 v = Ag[f];
        int db = seg * 4;
        Asm[(db + 0) * APAD + tok] = v.x;
        Asm[(db + 1) * APAD + tok] = v.y;
        Asm[(db + 2) * APAD + tok] = v.z;
        Asm[(db + 3) * APAD + tok] = v.w;
    }
    __syncthreads();

    unsigned long long hacc[4][8];
    #pragma unroll
    for (int r = 0; r < 4; r++)
        #pragma unroll
        for (int u = 0; u < 8; u++) hacc[r][u] = 0ull;

    for (int nb = 0; nb < 4; nb++) {
        int n0 = nb * 64;
        for (int dc = 0; dc < 16; dc++) {
            int dk = tid >> 4, nseg = tid & 15;
            float4 v = *reinterpret_cast<const float4*>(&W1[(size_t)(dc * 16 + dk) * SEMD + n0 + nseg * 4]);
            *reinterpret_cast<float4*>(&Bs[dk * APAD + nseg * 4]) = v;
            __syncthreads();
            #pragma unroll
            for (int kk = 0; kk < 16; kk++) {
                float4 av = *reinterpret_cast<const float4*>(&Asm[(dc * 16 + kk) * APAD + ty * 4]);
                ulonglong2 bb = *reinterpret_cast<const ulonglong2*>(&Bs[kk * APAD + tx * 4]);
                float a[4] = {av.x, av.y, av.z, av.w};
                #pragma unroll
                for (int r = 0; r < 4; r++) {
                    unsigned long long a2 = dup2(a[r]);
                    fma2(hacc[r][nb * 2 + 0], a2, bb.x);
                    fma2(hacc[r][nb * 2 + 1], a2, bb.y);
                }
            }
            __syncthreads();
        }
    }

    #pragma unroll
    for (int r = 0; r < 4; r++)
        #pragma unroll
        for (int u = 0; u < 8; u++) {
            int m = ty * 4 + r;
            int n = (u >> 1) * 64 + tx * 4 + (u & 1) * 2;
            float lo, hi;
            unpk(lo, hi, hacc[r][u]);
            float x0 = lo + __ldg(&b1[n]);
            float x1 = hi + __ldg(&b1[n + 1]);
            Asm[n * APAD + m]       = 0.5f * x0 * (1.0f + erff(x0 * 0.70710678118654752f));
            Asm[(n + 1) * APAD + m] = 0.5f * x1 * (1.0f + erff(x1 * 0.70710678118654752f));
        }
    __syncthreads();

    float ls = 0.f;
    for (int n0b = 0; n0b < 16; n0b++) {
        int n0 = n0b * 64;
        unsigned long long acc[4][2];
        #pragma unroll
        for (int r = 0; r < 4; r++) { acc[r][0] = 0ull; acc[r][1] = 0ull; }

        for (int dc = 0; dc < 16; dc++) {
            int dk = tid >> 4, nseg = tid & 15;
            float4 v = *reinterpret_cast<const float4*>(&W2[(size_t)(dc * 16 + dk) * W2VD + n0 + nseg * 4]);
            *reinterpret_cast<float4*>(&Bs[dk * APAD + nseg * 4]) = v;
            __syncthreads();
            #pragma unroll
            for (int kk = 0; kk < 16; kk++) {
                float4 av = *reinterpret_cast<const float4*>(&Asm[(dc * 16 + kk) * APAD + ty * 4]);
                ulonglong2 bb = *reinterpret_cast<const ulonglong2*>(&Bs[kk * APAD + tx * 4]);
                float a[4] = {av.x, av.y, av.z, av.w};
                #pragma unroll
                for (int r = 0; r < 4; r++) {
                    unsigned long long a2 = dup2(a[r]);
                    fma2(acc[r][0], a2, bb.x);
                    fma2(acc[r][1], a2, bb.y);
                }
            }
            __syncthreads();
        }

        #pragma unroll
        for (int r = 0; r < 4; r++)
            #pragma unroll
            for (int q = 0; q < 2; q++) {
                int m = m0 + ty * 4 + r, n = n0 + tx * 4 + q * 2;
                float lo, hi;
                unpk(lo, hi, acc[r][q]);
                float p0 = lo + __ldg(&b2[n]);
                float p1 = hi + __ldg(&b2[n + 1]);
                float d0 = p0 - __ldg(&tgt[(size_t)m * W2VD + n]);
                float d1 = p1 - __ldg(&tgt[(size_t)m * W2VD + n + 1]);
                ls += d0 * d0;
                ls += d1 * d1;
            }
    }

    __shared__ float red[8];
    int lane = tid & 31, w = tid >> 5;
    #pragma unroll
    for (int off = 16; off; off >>= 1) ls += __shfl_xor_sync(0xffffffffu, ls, off);
    if (!lane) red[w] = ls;
    __syncthreads();
    if (tid < 8) {
        float t = red[tid];
        #pragma unroll
        for (int off = 4; off; off >>= 1) t += __shfl_xor_sync(0xffu, t, off);
        if (tid == 0) atomicAdd(&g_semsum, t);
    }
}

// ---------------- finalize scalars ----------------
__global__ void k_fin(float* __restrict__ out) {
    if (threadIdx.x == 0) {
        float vq = 0.f;
        #pragma unroll
        for (int i = 0; i < NCB; i++) {
            float m = g_vqp[i] * (1.0f / 4194304.0f);
            vq += m + 0.25f * m;
        }
        out[VQ_OFF] = vq;
        out[SEM_OFF] = g_semsum * (1.0f / 16777216.0f);
    }
}

// ---------------- launch ----------------
extern "C" void kernel_launch(void* const* d_in, const int* in_sizes, int n_in,
                              void* d_out, int out_size) {
    const float* z   = (const float*)d_in[0];
    const float* w2v = (const float*)d_in[1];
    const float* E   = (const float*)d_in[2];
    const float* W1  = (const float*)d_in[3];
    const float* b1  = (const float*)d_in[4];
    const float* W2  = (const float*)d_in[5];
    const float* b2  = (const float*)d_in[6];
    float* out = (float*)d_out;

    const int SCR_SMEM = SB_TOT * 4;                     // 154,112 B
    const int SEM_SMEM = (256 * APAD + 16 * APAD) * 4;   // 73,984 B
    cudaFuncSetAttribute(k_scr, cudaFuncAttributeMaxDynamicSharedMemorySize, SCR_SMEM);
    cudaFuncSetAttribute(k_sem, cudaFuncAttributeMaxDynamicSharedMemorySize, SEM_SMEM);

    k_bfe<<<(NCB * KCB * DD) / 256, 256>>>(E);
    k_enorm<<<(NCB * KCB * 32 + 255) / 256, 256>>>(E);
    k_init<<<1, 32>>>();

    k_scr<<<148, 256, SCR_SMEM>>>(z, E, out);

    k_sem<<<BT / 64, 256, SEM_SMEM>>>(W1, b1, W2, b2, w2v);
    k_fin<<<1, 32>>>(out);
}